// round 9
// baseline (speedup 1.0000x reference)
#include <cuda_runtime.h>
#include <cuda_bf16.h>
#include <cstdint>

#define IN_DIM  128
#define HID_DIM 128
#define OUT_DIM 64
#define MAX_N   100000
#define MAX_E   1700000
#define STRIDE  96

// ---------------- device scratch ----------------
__device__ int   g_cnt[MAX_N];                    // in-degree (no self loop)
__device__ float g_dinv[MAX_N];
__device__ float g_s[MAX_N];
__device__ int   g_bin2[(size_t)MAX_N * STRIDE];  // fixed-stride in-neighbor bins
__device__ __nv_bfloat16 g_h0bf[(size_t)MAX_N * HID_DIM];  // dinv[v]*(x@W1)[v]
__device__ float g_y[HID_DIM];
__device__ int   g_is32;

__device__ __forceinline__ int load_idx(const void* ei, size_t i) {
    if (g_is32) return ((const int*)ei)[i];
    return (int)((const long long*)ei)[i];
}

// ------------- init: zero counters + dtype detect + zero y -----------
__global__ void init_kernel(const void* ei, int n) {
    int i = blockIdx.x * blockDim.x + threadIdx.x;
    if (i < n) g_cnt[i] = 0;
    if (i < 128) g_y[i] = 0.f;
    if (i == 0) {
        const long long* p = (const long long*)ei;
        int bad = 0;
        for (int k = 0; k < 8; k++) {
            long long v = p[k];
            if (v < 0 || v >= (long long)n) bad = 1;
        }
        g_is32 = bad;
    }
}

// ------------- binA: one edge pass does count + bin fill -------------
__global__ void binA_kernel(const void* ei, int E) {
    int e = blockIdx.x * blockDim.x + threadIdx.x;
    if (e >= E) return;
    int r = load_idx(ei, e);
    int c = load_idx(ei, (size_t)E + e);
    int pos = atomicAdd(&g_cnt[c], 1);
    if (pos < STRIDE) g_bin2[(unsigned)c * STRIDE + pos] = r;
}

// ------------- dinv from counts (for conv) -------------
__global__ void dinv_kernel(int n) {
    int i = blockIdx.x * blockDim.x + threadIdx.x;
    if (i < n) {
        float d = rsqrtf((float)(g_cnt[i] + 1));
        g_dinv[i] = d;
        g_s[i] = d;
    }
}

// ---- GEMM1: h0' = bf16(dinv[row] * (x @ W1)); 64-row tiles for occupancy ----
#define AS_STRIDE 136
__global__ __launch_bounds__(256) void gemm1_kernel(
    const float* __restrict__ x, const float* __restrict__ W, int n)
{
    __shared__ __nv_bfloat16 As[64][AS_STRIDE];    // 17.4 KB
    __shared__ __nv_bfloat16 Ws[128][AS_STRIDE];   // 34.8 KB, transposed [n][k]
    int t = threadIdx.x;
    int row0 = blockIdx.x * 64;

    const float4* xg = (const float4*)x;
    #pragma unroll
    for (int i = 0; i < 8; i++) {
        int idx4 = t + i * 256;
        int r = idx4 >> 5, c4 = idx4 & 31;
        float4 v = make_float4(0.f, 0.f, 0.f, 0.f);
        if (row0 + r < n) v = xg[(size_t)(row0 + r) * 32 + c4];
        *(__nv_bfloat162*)&As[r][c4 * 4]     = __floats2bfloat162_rn(v.x, v.y);
        *(__nv_bfloat162*)&As[r][c4 * 4 + 2] = __floats2bfloat162_rn(v.z, v.w);
    }
    const float4* wg = (const float4*)W;
    #pragma unroll
    for (int i = 0; i < 16; i++) {
        int idx4 = t + i * 256;
        int k = idx4 >> 5, n4 = idx4 & 31;
        float4 v = wg[idx4];
        Ws[n4 * 4 + 0][k] = __float2bfloat16(v.x);
        Ws[n4 * 4 + 1][k] = __float2bfloat16(v.y);
        Ws[n4 * 4 + 2][k] = __float2bfloat16(v.z);
        Ws[n4 * 4 + 3][k] = __float2bfloat16(v.w);
    }
    __syncthreads();

    int lane = t & 31, wid = t >> 5;
    int moff = (wid & 3) * 16;      // 4 M-groups x 16 rows = 64
    int noff = (wid >> 2) * 64;     // 2 N-groups x 64 cols
    int g = lane >> 2, tq = lane & 3;

    float acc[8][4];
    #pragma unroll
    for (int nt = 0; nt < 8; nt++)
        #pragma unroll
        for (int j = 0; j < 4; j++) acc[nt][j] = 0.f;

    #pragma unroll
    for (int kt = 0; kt < 8; kt++) {
        int k0 = kt * 16;
        int r = moff + g;
        uint32_t a0 = *(const uint32_t*)&As[r][k0 + 2 * tq];
        uint32_t a1 = *(const uint32_t*)&As[r + 8][k0 + 2 * tq];
        uint32_t a2 = *(const uint32_t*)&As[r][k0 + 2 * tq + 8];
        uint32_t a3 = *(const uint32_t*)&As[r + 8][k0 + 2 * tq + 8];
        #pragma unroll
        for (int nt = 0; nt < 8; nt++) {
            int c = noff + nt * 8 + g;
            uint32_t b0 = *(const uint32_t*)&Ws[c][k0 + 2 * tq];
            uint32_t b1 = *(const uint32_t*)&Ws[c][k0 + 2 * tq + 8];
            asm volatile(
                "mma.sync.aligned.m16n8k16.row.col.f32.bf16.bf16.f32 "
                "{%0,%1,%2,%3}, {%4,%5,%6,%7}, {%8,%9}, {%0,%1,%2,%3};"
                : "+f"(acc[nt][0]), "+f"(acc[nt][1]),
                  "+f"(acc[nt][2]), "+f"(acc[nt][3])
                : "r"(a0), "r"(a1), "r"(a2), "r"(a3),
                  "r"(b0), "r"(b1));
        }
    }

    {
        int r = row0 + moff + g;
        float d0 = (r < n) ? rsqrtf((float)(g_cnt[r] + 1)) : 0.f;
        float d1 = (r + 8 < n) ? rsqrtf((float)(g_cnt[r + 8] + 1)) : 0.f;
        #pragma unroll
        for (int nt = 0; nt < 8; nt++) {
            int c = noff + nt * 8 + 2 * tq;
            if (r < n)
                *(__nv_bfloat162*)&g_h0bf[(size_t)r * 128 + c] =
                    __floats2bfloat162_rn(d0 * acc[nt][0], d0 * acc[nt][1]);
            if (r + 8 < n)
                *(__nv_bfloat162*)&g_h0bf[(size_t)(r + 8) * 128 + c] =
                    __floats2bfloat162_rn(d1 * acc[nt][2], d1 * acc[nt][3]);
        }
    }
}

// ------------- sacc: s[r] += dinv[c] per edge (dinv computed inline) -------
__global__ void sacc_kernel(const void* ei, int E) {
    int e = blockIdx.x * blockDim.x + threadIdx.x;
    if (e >= E) return;
    int r = load_idx(ei, e);
    int c = load_idx(ei, (size_t)E + e);
    float dc = rsqrtf((float)(__ldcg(&g_cnt[c]) + 1));
    atomicAdd(&g_s[r], dc);
}

// ---------------- fused conv1 + relu + weighted reduce ---------------------
__device__ __forceinline__ void add4bf(float4& a, uint2 u) {
    float2 f0 = __bfloat1622float2(*(__nv_bfloat162*)&u.x);
    float2 f1 = __bfloat1622float2(*(__nv_bfloat162*)&u.y);
    a.x += f0.x; a.y += f0.y; a.z += f1.x; a.w += f1.y;
}

__global__ __launch_bounds__(256) void fused_conv_kernel(
    const float* __restrict__ b1, int n)
{
    __shared__ float ysh[8 * 128];
    int t = threadIdx.x, lane = t & 31, w = t >> 5;
    float4 bb = ((const float4*)b1)[lane];
    float4 yacc = make_float4(0.f, 0.f, 0.f, 0.f);
    const uint2* h = (const uint2*)g_h0bf;   // 32 x 8B per row

    int gw = blockIdx.x * 8 + w;
    int nw = gridDim.x * 8;
    for (int v = gw; v < n; v += nw) {
        float dv = g_dinv[v];
        int cnt = min(g_cnt[v], STRIDE);
        unsigned binrow = (unsigned)v * STRIDE;

        float4 a0 = make_float4(0.f, 0.f, 0.f, 0.f);
        float4 a1 = a0;
        add4bf(a0, h[(unsigned)v * 32 + lane]);   // self loop (h already *dinv)

        for (int kb = 0; kb < cnt; kb += 32) {
            int m = min(cnt - kb, 32);
            int myidx = (lane < m) ? g_bin2[binrow + kb + lane] : 0;  // coalesced
            int j = 0;
            for (; j + 2 <= m; j += 2) {
                int s0 = __shfl_sync(0xffffffffu, myidx, j);
                int s1 = __shfl_sync(0xffffffffu, myidx, j + 1);
                uint2 u0 = h[(unsigned)s0 * 32 + lane];
                uint2 u1 = h[(unsigned)s1 * 32 + lane];
                add4bf(a0, u0);
                add4bf(a1, u1);
            }
            if (j < m) {
                int s0 = __shfl_sync(0xffffffffu, myidx, j);
                add4bf(a1, h[(unsigned)s0 * 32 + lane]);
            }
        }

        float cv = dv * g_s[v];
        yacc.x = fmaf(cv, fmaxf(fmaf(dv, a0.x + a1.x, bb.x), 0.f), yacc.x);
        yacc.y = fmaf(cv, fmaxf(fmaf(dv, a0.y + a1.y, bb.y), 0.f), yacc.y);
        yacc.z = fmaf(cv, fmaxf(fmaf(dv, a0.z + a1.z, bb.z), 0.f), yacc.z);
        yacc.w = fmaf(cv, fmaxf(fmaf(dv, a0.w + a1.w, bb.w), 0.f), yacc.w);
    }

    *((float4*)&ysh[w * 128 + lane * 4]) = yacc;
    __syncthreads();
    if (t < 128) {
        float s = 0.f;
        #pragma unroll
        for (int i = 0; i < 8; i++) s += ysh[i * 128 + t];
        atomicAdd(&g_y[t], s);
    }
}

// ---------------- final: out = (y @ W2)/N + b2 ----------------
__global__ void final_kernel(const float* __restrict__ W2,
                             const float* __restrict__ b2,
                             float* __restrict__ out, int n)
{
    int f = threadIdx.x;   // 64
    float sum = 0.f;
    #pragma unroll 8
    for (int k = 0; k < 128; k++)
        sum = fmaf(g_y[k], W2[k * 64 + f], sum);
    out[f] = sum / (float)n + b2[f];
}

// ---------------- launch ----------------
extern "C" void kernel_launch(void* const* d_in, const int* in_sizes, int n_in,
                              void* d_out, int out_size)
{
    const float* x  = (const float*)d_in[0];
    const void*  ei = d_in[1];
    const float* W1 = (const float*)d_in[2];
    const float* b1 = (const float*)d_in[3];
    const float* W2 = (const float*)d_in[4];
    const float* b2 = (const float*)d_in[5];
    float* out = (float*)d_out;

    int n = in_sizes[0] / IN_DIM;     // 100000
    int E = in_sizes[1] / 2;          // 1600000

    init_kernel<<<(n + 255) / 256, 256>>>(ei, n);          // idx 0
    binA_kernel<<<(E + 255) / 256, 256>>>(ei, E);          // idx 1
    dinv_kernel<<<(n + 255) / 256, 256>>>(n);              // idx 2
    gemm1_kernel<<<(n + 63) / 64, 256>>>(x, W1, n);        // idx 3 (profiled)
    sacc_kernel<<<(E + 255) / 256, 256>>>(ei, E);          // idx 4
    fused_conv_kernel<<<1776, 256>>>(b1, n);               // idx 5
    final_kernel<<<1, 64>>>(W2, b2, out, n);               // idx 6
}

// round 10
// speedup vs baseline: 1.0775x; 1.0775x over previous
#include <cuda_runtime.h>
#include <cuda_bf16.h>
#include <cstdint>

#define IN_DIM  128
#define HID_DIM 128
#define OUT_DIM 64
#define MAX_N   100000
#define MAX_E   1700000
#define STRIDE  96

// ---------------- device scratch ----------------
__device__ int   g_cnt[MAX_N];                    // in-degree (no self loop)
__device__ float g_dinv[MAX_N];
__device__ float g_s[MAX_N];
__device__ int   g_bin2[(size_t)MAX_N * STRIDE];  // fixed-stride in-neighbor bins
__device__ __nv_bfloat16 g_h0bf[(size_t)MAX_N * HID_DIM];  // dinv[v]*(x@W1)[v]
__device__ float g_y[HID_DIM];
__device__ int   g_is32;

__device__ __forceinline__ int load_idx(const void* ei, size_t i) {
    if (g_is32) return ((const int*)ei)[i];
    return (int)((const long long*)ei)[i];
}

// ------------- init: zero counters + dtype detect + zero y -----------
__global__ void init_kernel(const void* ei, int n) {
    int i = blockIdx.x * blockDim.x + threadIdx.x;
    if (i < n) g_cnt[i] = 0;
    if (i < 128) g_y[i] = 0.f;
    if (i == 0) {
        const long long* p = (const long long*)ei;
        int bad = 0;
        for (int k = 0; k < 8; k++) {
            long long v = p[k];
            if (v < 0 || v >= (long long)n) bad = 1;
        }
        g_is32 = bad;
    }
}

// ------------- binA: one edge pass does count + bin fill -------------
__global__ void binA_kernel(const void* ei, int E) {
    int e = blockIdx.x * blockDim.x + threadIdx.x;
    if (e >= E) return;
    int r = load_idx(ei, e);
    int c = load_idx(ei, (size_t)E + e);
    int pos = atomicAdd(&g_cnt[c], 1);
    if (pos < STRIDE) g_bin2[(unsigned)c * STRIDE + pos] = r;
}

// ------------- dinv from counts -------------
__global__ void dinv_kernel(int n) {
    int i = blockIdx.x * blockDim.x + threadIdx.x;
    if (i < n) {
        float d = rsqrtf((float)(g_cnt[i] + 1));
        g_dinv[i] = d;
        g_s[i] = d;
    }
}

// ---- GEMM1: h0' = bf16(dinv[row]*(x @ W1)); A direct from gmem, B in smem ----
#define AS_STRIDE 136
__device__ __forceinline__ uint32_t packbf(float2 v) {
    __nv_bfloat162 b = __floats2bfloat162_rn(v.x, v.y);
    return *(uint32_t*)&b;
}

__global__ __launch_bounds__(256) void gemm1_kernel(
    const float* __restrict__ x, const float* __restrict__ W, int n)
{
    __shared__ __nv_bfloat16 Ws[128][AS_STRIDE];   // transposed [n][k], 34.8 KB
    int t = threadIdx.x;
    int row0 = blockIdx.x * 128;

    const float4* wg = (const float4*)W;
    #pragma unroll
    for (int i = 0; i < 16; i++) {
        int idx4 = t + i * 256;
        int k = idx4 >> 5, n4 = idx4 & 31;
        float4 v = wg[idx4];
        Ws[n4 * 4 + 0][k] = __float2bfloat16(v.x);
        Ws[n4 * 4 + 1][k] = __float2bfloat16(v.y);
        Ws[n4 * 4 + 2][k] = __float2bfloat16(v.z);
        Ws[n4 * 4 + 3][k] = __float2bfloat16(v.w);
    }
    __syncthreads();

    int lane = t & 31, wid = t >> 5;
    int moff = (wid & 3) * 32;      // 4 M-groups x 32 rows
    int noff = (wid >> 2) * 64;     // 2 N-groups x 64 cols
    int g = lane >> 2, tq = lane & 3;

    // row pointers (clamped: rows >= n read row n-1, discarded in epilogue)
    int rr[4];
    rr[0] = row0 + moff + g;
    rr[1] = rr[0] + 8;
    rr[2] = rr[0] + 16;
    rr[3] = rr[0] + 24;
    const float* xp[4];
    #pragma unroll
    for (int i = 0; i < 4; i++) {
        int rc = rr[i] < n ? rr[i] : (n - 1);
        xp[i] = x + (size_t)rc * 128 + 2 * tq;
    }

    float acc[2][8][4];
    #pragma unroll
    for (int mt = 0; mt < 2; mt++)
        #pragma unroll
        for (int nt = 0; nt < 8; nt++)
            #pragma unroll
            for (int j = 0; j < 4; j++) acc[mt][nt][j] = 0.f;

    #pragma unroll
    for (int kt = 0; kt < 8; kt++) {
        int k0 = kt * 16;
        uint32_t a[2][4];
        // direct gmem A fragments: float2 -> bf16x2 in registers
        #pragma unroll
        for (int mt = 0; mt < 2; mt++) {
            float2 v0 = *(const float2*)(xp[mt * 2]     + k0);
            float2 v1 = *(const float2*)(xp[mt * 2 + 1] + k0);
            float2 v2 = *(const float2*)(xp[mt * 2]     + k0 + 8);
            float2 v3 = *(const float2*)(xp[mt * 2 + 1] + k0 + 8);
            a[mt][0] = packbf(v0);
            a[mt][1] = packbf(v1);
            a[mt][2] = packbf(v2);
            a[mt][3] = packbf(v3);
        }
        #pragma unroll
        for (int nt = 0; nt < 8; nt++) {
            int c = noff + nt * 8 + g;
            uint32_t b0 = *(const uint32_t*)&Ws[c][k0 + 2 * tq];
            uint32_t b1 = *(const uint32_t*)&Ws[c][k0 + 2 * tq + 8];
            #pragma unroll
            for (int mt = 0; mt < 2; mt++) {
                asm volatile(
                    "mma.sync.aligned.m16n8k16.row.col.f32.bf16.bf16.f32 "
                    "{%0,%1,%2,%3}, {%4,%5,%6,%7}, {%8,%9}, {%0,%1,%2,%3};"
                    : "+f"(acc[mt][nt][0]), "+f"(acc[mt][nt][1]),
                      "+f"(acc[mt][nt][2]), "+f"(acc[mt][nt][3])
                    : "r"(a[mt][0]), "r"(a[mt][1]), "r"(a[mt][2]), "r"(a[mt][3]),
                      "r"(b0), "r"(b1));
            }
        }
    }

    #pragma unroll
    for (int mt = 0; mt < 2; mt++) {
        int r = rr[mt * 2];
        float d0 = (r < n) ? g_dinv[r] : 0.f;
        float d1 = (r + 8 < n) ? g_dinv[r + 8] : 0.f;
        #pragma unroll
        for (int nt = 0; nt < 8; nt++) {
            int c = noff + nt * 8 + 2 * tq;
            if (r < n)
                *(__nv_bfloat162*)&g_h0bf[(size_t)r * 128 + c] =
                    __floats2bfloat162_rn(d0 * acc[mt][nt][0], d0 * acc[mt][nt][1]);
            if (r + 8 < n)
                *(__nv_bfloat162*)&g_h0bf[(size_t)(r + 8) * 128 + c] =
                    __floats2bfloat162_rn(d1 * acc[mt][nt][2], d1 * acc[mt][nt][3]);
        }
    }
}

// ------------- sacc from bins: s[src] += dinv[v] for src in bin[v] ---------
__global__ void sacc_kernel(int n) {
    int w = (blockIdx.x * blockDim.x + threadIdx.x) >> 5;
    int lane = threadIdx.x & 31;
    if (w >= n) return;
    float dv = g_dinv[w];
    int cnt = min(g_cnt[w], STRIDE);
    unsigned base = (unsigned)w * STRIDE;
    for (int k = lane; k < cnt; k += 32)
        atomicAdd(&g_s[g_bin2[base + k]], dv);
}

// ---------------- fused conv1 + relu + weighted reduce ---------------------
__device__ __forceinline__ void add4bf(float4& a, uint2 u) {
    float2 f0 = __bfloat1622float2(*(__nv_bfloat162*)&u.x);
    float2 f1 = __bfloat1622float2(*(__nv_bfloat162*)&u.y);
    a.x += f0.x; a.y += f0.y; a.z += f1.x; a.w += f1.y;
}

__global__ __launch_bounds__(256) void fused_conv_kernel(
    const float* __restrict__ b1, int n)
{
    __shared__ float ysh[8 * 128];
    int t = threadIdx.x, lane = t & 31, w = t >> 5;
    float4 bb = ((const float4*)b1)[lane];
    float4 yacc = make_float4(0.f, 0.f, 0.f, 0.f);
    const uint2* h = (const uint2*)g_h0bf;   // 32 x 8B per row

    int gw = blockIdx.x * 8 + w;
    int nw = gridDim.x * 8;
    for (int v = gw; v < n; v += nw) {
        float dv = g_dinv[v];
        int cnt = min(g_cnt[v], STRIDE);
        unsigned binrow = (unsigned)v * STRIDE;

        float4 a0 = make_float4(0.f, 0.f, 0.f, 0.f);
        float4 a1 = a0;
        add4bf(a0, h[(unsigned)v * 32 + lane]);   // self loop (h already *dinv)

        for (int kb = 0; kb < cnt; kb += 32) {
            int m = min(cnt - kb, 32);
            int myidx = (lane < m) ? g_bin2[binrow + kb + lane] : 0;  // coalesced
            int j = 0;
            for (; j + 2 <= m; j += 2) {
                int s0 = __shfl_sync(0xffffffffu, myidx, j);
                int s1 = __shfl_sync(0xffffffffu, myidx, j + 1);
                uint2 u0 = h[(unsigned)s0 * 32 + lane];
                uint2 u1 = h[(unsigned)s1 * 32 + lane];
                add4bf(a0, u0);
                add4bf(a1, u1);
            }
            if (j < m) {
                int s0 = __shfl_sync(0xffffffffu, myidx, j);
                add4bf(a1, h[(unsigned)s0 * 32 + lane]);
            }
        }

        float cv = dv * g_s[v];
        yacc.x = fmaf(cv, fmaxf(fmaf(dv, a0.x + a1.x, bb.x), 0.f), yacc.x);
        yacc.y = fmaf(cv, fmaxf(fmaf(dv, a0.y + a1.y, bb.y), 0.f), yacc.y);
        yacc.z = fmaf(cv, fmaxf(fmaf(dv, a0.z + a1.z, bb.z), 0.f), yacc.z);
        yacc.w = fmaf(cv, fmaxf(fmaf(dv, a0.w + a1.w, bb.w), 0.f), yacc.w);
    }

    *((float4*)&ysh[w * 128 + lane * 4]) = yacc;
    __syncthreads();
    if (t < 128) {
        float s = 0.f;
        #pragma unroll
        for (int i = 0; i < 8; i++) s += ysh[i * 128 + t];
        atomicAdd(&g_y[t], s);
    }
}

// ---------------- final: out = (y @ W2)/N + b2 ----------------
__global__ void final_kernel(const float* __restrict__ W2,
                             const float* __restrict__ b2,
                             float* __restrict__ out, int n)
{
    int f = threadIdx.x;   // 64
    float sum = 0.f;
    #pragma unroll 8
    for (int k = 0; k < 128; k++)
        sum = fmaf(g_y[k], W2[k * 64 + f], sum);
    out[f] = sum / (float)n + b2[f];
}

// ---------------- launch ----------------
extern "C" void kernel_launch(void* const* d_in, const int* in_sizes, int n_in,
                              void* d_out, int out_size)
{
    const float* x  = (const float*)d_in[0];
    const void*  ei = d_in[1];
    const float* W1 = (const float*)d_in[2];
    const float* b1 = (const float*)d_in[3];
    const float* W2 = (const float*)d_in[4];
    const float* b2 = (const float*)d_in[5];
    float* out = (float*)d_out;

    int n = in_sizes[0] / IN_DIM;     // 100000
    int E = in_sizes[1] / 2;          // 1600000

    init_kernel<<<(n + 255) / 256, 256>>>(ei, n);          // idx 0
    binA_kernel<<<(E + 255) / 256, 256>>>(ei, E);          // idx 1
    dinv_kernel<<<(n + 255) / 256, 256>>>(n);              // idx 2
    gemm1_kernel<<<(n + 127) / 128, 256>>>(x, W1, n);      // idx 3 (profiled)
    sacc_kernel<<<(n * 32 + 255) / 256, 256>>>(n);         // idx 4
    fused_conv_kernel<<<1776, 256>>>(b1, n);               // idx 5
    final_kernel<<<1, 64>>>(W2, b2, out, n);               // idx 6
}

// round 11
// speedup vs baseline: 1.3020x; 1.2084x over previous
#include <cuda_runtime.h>
#include <cuda_bf16.h>
#include <cstdint>

#define IN_DIM  128
#define HID_DIM 128
#define OUT_DIM 64
#define MAX_N   100000
#define MAX_E   1700000
#define STRIDE  96

#define WS_BYTES   (128 * 136 * 2)            // 34816
#define AS_PITCH   132
#define AS_BYTES   (64 * AS_PITCH * 4)        // 33792 per buffer
#define GEMM_SMEM  (WS_BYTES + 2 * AS_BYTES)  // 102400
#define GEMM_GRID  296

// ---------------- device scratch ----------------
__device__ int   g_cnt[MAX_N];                    // in-degree (no self loop)
__device__ float g_dinv[MAX_N];
__device__ float g_s[MAX_N];
__device__ int   g_bin2[(size_t)MAX_N * STRIDE];  // fixed-stride in-neighbor bins
__device__ __nv_bfloat16 g_h0bf[(size_t)MAX_N * HID_DIM];  // dinv[v]*(x@W1)[v]
__device__ float g_y[HID_DIM];
__device__ int   g_is32;

__device__ __forceinline__ int load_idx(const void* ei, size_t i) {
    if (g_is32) return ((const int*)ei)[i];
    return (int)((const long long*)ei)[i];
}

// ------------- init: zero counters + dtype detect + zero y -----------
__global__ void init_kernel(const void* ei, int n) {
    int i = blockIdx.x * blockDim.x + threadIdx.x;
    if (i < n) g_cnt[i] = 0;
    if (i < 128) g_y[i] = 0.f;
    if (i == 0) {
        const long long* p = (const long long*)ei;
        int bad = 0;
        for (int k = 0; k < 8; k++) {
            long long v = p[k];
            if (v < 0 || v >= (long long)n) bad = 1;
        }
        g_is32 = bad;
    }
}

// ------------- binA: one edge pass does count + bin fill -------------
__global__ void binA_kernel(const void* ei, int E) {
    int e = blockIdx.x * blockDim.x + threadIdx.x;
    if (e >= E) return;
    int r = load_idx(ei, e);
    int c = load_idx(ei, (size_t)E + e);
    int pos = atomicAdd(&g_cnt[c], 1);
    if (pos < STRIDE) g_bin2[(unsigned)c * STRIDE + pos] = r;
}

// ------------- dinv from counts -------------
__global__ void dinv_kernel(int n) {
    int i = blockIdx.x * blockDim.x + threadIdx.x;
    if (i < n) {
        float d = rsqrtf((float)(g_cnt[i] + 1));
        g_dinv[i] = d;
        g_s[i] = d;
    }
}

// ---- GEMM1: persistent CTAs, cp.async double-buffered 64-row tiles ----
__device__ __forceinline__ uint32_t packbf(float2 v) {
    __nv_bfloat162 b = __floats2bfloat162_rn(v.x, v.y);
    return *(uint32_t*)&b;
}

__device__ __forceinline__ void cpasync16(void* dst, const void* src) {
    uint32_t d = (uint32_t)__cvta_generic_to_shared(dst);
    asm volatile("cp.async.cg.shared.global [%0], [%1], 16;" :: "r"(d), "l"(src));
}

__global__ __launch_bounds__(256) void gemm1_kernel(
    const float* __restrict__ x, const float* __restrict__ W, int n)
{
    extern __shared__ char smem[];
    __nv_bfloat16 (*Ws)[136] = (__nv_bfloat16(*)[136])smem;          // [128][136]
    float* As = (float*)(smem + WS_BYTES);   // 2 buffers of [64][AS_PITCH]

    int t = threadIdx.x;
    int ntiles = (n + 63) >> 6;

    // load W (once): transposed bf16 [n][k]
    const float4* wg = (const float4*)W;
    #pragma unroll
    for (int i = 0; i < 16; i++) {
        int idx4 = t + i * 256;
        int k = idx4 >> 5, n4 = idx4 & 31;
        float4 v = wg[idx4];
        Ws[n4 * 4 + 0][k] = __float2bfloat16(v.x);
        Ws[n4 * 4 + 1][k] = __float2bfloat16(v.y);
        Ws[n4 * 4 + 2][k] = __float2bfloat16(v.z);
        Ws[n4 * 4 + 3][k] = __float2bfloat16(v.w);
    }

    int lane = t & 31, wid = t >> 5;
    int moff = (wid & 3) * 16;      // 4 M-groups x 16 rows = 64
    int noff = (wid >> 2) * 64;     // 2 N-groups x 64 cols
    int g = lane >> 2, tq = lane & 3;

    // prefetch first tile into buf 0
    int tile0 = blockIdx.x;
    {
        int row0 = tile0 < ntiles ? tile0 * 64 : 0;
        #pragma unroll
        for (int i = 0; i < 8; i++) {
            int idx = t + i * 256;           // 2048 float4 slots
            int r = idx >> 5, c4 = idx & 31;
            int grow = row0 + r; if (grow >= n) grow = n - 1;
            cpasync16(&As[r * AS_PITCH + c4 * 4],
                      x + (size_t)grow * 128 + c4 * 4);
        }
        asm volatile("cp.async.commit_group;");
    }
    __syncthreads();   // Ws ready (also joins prologue)

    int buf = 0;
    for (int tile = tile0; tile < ntiles; tile += GEMM_GRID) {
        // prefetch next tile into buf^1
        {
            int nt2 = tile + GEMM_GRID;
            int row0 = (nt2 < ntiles) ? nt2 * 64 : tile * 64;
            float* dstb = As + (buf ^ 1) * (64 * AS_PITCH);
            #pragma unroll
            for (int i = 0; i < 8; i++) {
                int idx = t + i * 256;
                int r = idx >> 5, c4 = idx & 31;
                int grow = row0 + r; if (grow >= n) grow = n - 1;
                cpasync16(&dstb[r * AS_PITCH + c4 * 4],
                          x + (size_t)grow * 128 + c4 * 4);
            }
            asm volatile("cp.async.commit_group;");
        }
        asm volatile("cp.async.wait_group 1;");   // current tile resident
        __syncthreads();

        const float* Ab = As + buf * (64 * AS_PITCH);
        float acc[8][4];
        #pragma unroll
        for (int nt = 0; nt < 8; nt++)
            #pragma unroll
            for (int j = 0; j < 4; j++) acc[nt][j] = 0.f;

        #pragma unroll
        for (int kt = 0; kt < 8; kt++) {
            int k0 = kt * 16;
            int r = moff + g;
            uint32_t a0 = packbf(*(const float2*)&Ab[r * AS_PITCH + k0 + 2 * tq]);
            uint32_t a1 = packbf(*(const float2*)&Ab[(r + 8) * AS_PITCH + k0 + 2 * tq]);
            uint32_t a2 = packbf(*(const float2*)&Ab[r * AS_PITCH + k0 + 2 * tq + 8]);
            uint32_t a3 = packbf(*(const float2*)&Ab[(r + 8) * AS_PITCH + k0 + 2 * tq + 8]);
            #pragma unroll
            for (int nt = 0; nt < 8; nt++) {
                int c = noff + nt * 8 + g;
                uint32_t b0 = *(const uint32_t*)&Ws[c][k0 + 2 * tq];
                uint32_t b1 = *(const uint32_t*)&Ws[c][k0 + 2 * tq + 8];
                asm volatile(
                    "mma.sync.aligned.m16n8k16.row.col.f32.bf16.bf16.f32 "
                    "{%0,%1,%2,%3}, {%4,%5,%6,%7}, {%8,%9}, {%0,%1,%2,%3};"
                    : "+f"(acc[nt][0]), "+f"(acc[nt][1]),
                      "+f"(acc[nt][2]), "+f"(acc[nt][3])
                    : "r"(a0), "r"(a1), "r"(a2), "r"(a3),
                      "r"(b0), "r"(b1));
            }
        }

        // epilogue: scale by dinv, store bf16
        {
            int r = tile * 64 + moff + g;
            float d0 = (r < n) ? g_dinv[r] : 0.f;
            float d1 = (r + 8 < n) ? g_dinv[r + 8] : 0.f;
            #pragma unroll
            for (int nt = 0; nt < 8; nt++) {
                int c = noff + nt * 8 + 2 * tq;
                if (r < n)
                    *(__nv_bfloat162*)&g_h0bf[(size_t)r * 128 + c] =
                        __floats2bfloat162_rn(d0 * acc[nt][0], d0 * acc[nt][1]);
                if (r + 8 < n)
                    *(__nv_bfloat162*)&g_h0bf[(size_t)(r + 8) * 128 + c] =
                        __floats2bfloat162_rn(d1 * acc[nt][2], d1 * acc[nt][3]);
            }
        }
        __syncthreads();   // all reads of buf done before next prefetch overwrites
        buf ^= 1;
    }
}

// ------------- sacc from bins: s[src] += dinv[v] for src in bin[v] ---------
__global__ void sacc_kernel(int n) {
    int w = (blockIdx.x * blockDim.x + threadIdx.x) >> 5;
    int lane = threadIdx.x & 31;
    if (w >= n) return;
    float dv = g_dinv[w];
    int cnt = min(g_cnt[w], STRIDE);
    unsigned base = (unsigned)w * STRIDE;
    for (int k = lane; k < cnt; k += 32)
        atomicAdd(&g_s[g_bin2[base + k]], dv);
}

// ---------------- fused conv1 + relu + weighted reduce ---------------------
__device__ __forceinline__ void add4bf(float4& a, uint2 u) {
    float2 f0 = __bfloat1622float2(*(__nv_bfloat162*)&u.x);
    float2 f1 = __bfloat1622float2(*(__nv_bfloat162*)&u.y);
    a.x += f0.x; a.y += f0.y; a.z += f1.x; a.w += f1.y;
}

__global__ __launch_bounds__(256) void fused_conv_kernel(
    const float* __restrict__ b1, int n)
{
    __shared__ float ysh[8 * 128];
    int t = threadIdx.x, lane = t & 31, w = t >> 5;
    float4 bb = ((const float4*)b1)[lane];
    float4 yacc = make_float4(0.f, 0.f, 0.f, 0.f);
    const uint2* h = (const uint2*)g_h0bf;   // 32 x 8B per row

    int gw = blockIdx.x * 8 + w;
    int nw = gridDim.x * 8;
    for (int v = gw; v < n; v += nw) {
        float dv = g_dinv[v];
        int cnt = min(g_cnt[v], STRIDE);
        unsigned binrow = (unsigned)v * STRIDE;

        float4 a0 = make_float4(0.f, 0.f, 0.f, 0.f);
        float4 a1 = a0;
        add4bf(a0, h[(unsigned)v * 32 + lane]);   // self loop (h already *dinv)

        for (int kb = 0; kb < cnt; kb += 32) {
            int m = min(cnt - kb, 32);
            int myidx = (lane < m) ? g_bin2[binrow + kb + lane] : 0;  // coalesced
            int j = 0;
            for (; j + 2 <= m; j += 2) {
                int s0 = __shfl_sync(0xffffffffu, myidx, j);
                int s1 = __shfl_sync(0xffffffffu, myidx, j + 1);
                uint2 u0 = h[(unsigned)s0 * 32 + lane];
                uint2 u1 = h[(unsigned)s1 * 32 + lane];
                add4bf(a0, u0);
                add4bf(a1, u1);
            }
            if (j < m) {
                int s0 = __shfl_sync(0xffffffffu, myidx, j);
                add4bf(a1, h[(unsigned)s0 * 32 + lane]);
            }
        }

        float cv = dv * g_s[v];
        yacc.x = fmaf(cv, fmaxf(fmaf(dv, a0.x + a1.x, bb.x), 0.f), yacc.x);
        yacc.y = fmaf(cv, fmaxf(fmaf(dv, a0.y + a1.y, bb.y), 0.f), yacc.y);
        yacc.z = fmaf(cv, fmaxf(fmaf(dv, a0.z + a1.z, bb.z), 0.f), yacc.z);
        yacc.w = fmaf(cv, fmaxf(fmaf(dv, a0.w + a1.w, bb.w), 0.f), yacc.w);
    }

    *((float4*)&ysh[w * 128 + lane * 4]) = yacc;
    __syncthreads();
    if (t < 128) {
        float s = 0.f;
        #pragma unroll
        for (int i = 0; i < 8; i++) s += ysh[i * 128 + t];
        atomicAdd(&g_y[t], s);
    }
}

// ---------------- final: out = (y @ W2)/N + b2 ----------------
__global__ void final_kernel(const float* __restrict__ W2,
                             const float* __restrict__ b2,
                             float* __restrict__ out, int n)
{
    int f = threadIdx.x;   // 64
    float sum = 0.f;
    #pragma unroll 8
    for (int k = 0; k < 128; k++)
        sum = fmaf(g_y[k], W2[k * 64 + f], sum);
    out[f] = sum / (float)n + b2[f];
}

// ---------------- launch ----------------
extern "C" void kernel_launch(void* const* d_in, const int* in_sizes, int n_in,
                              void* d_out, int out_size)
{
    const float* x  = (const float*)d_in[0];
    const void*  ei = d_in[1];
    const float* W1 = (const float*)d_in[2];
    const float* b1 = (const float*)d_in[3];
    const float* W2 = (const float*)d_in[4];
    const float* b2 = (const float*)d_in[5];
    float* out = (float*)d_out;

    int n = in_sizes[0] / IN_DIM;     // 100000
    int E = in_sizes[1] / 2;          // 1600000

    cudaFuncSetAttribute(gemm1_kernel,
                         cudaFuncAttributeMaxDynamicSharedMemorySize, GEMM_SMEM);

    init_kernel<<<(n + 255) / 256, 256>>>(ei, n);              // idx 0
    binA_kernel<<<(E + 255) / 256, 256>>>(ei, E);              // idx 1
    dinv_kernel<<<(n + 255) / 256, 256>>>(n);                  // idx 2
    gemm1_kernel<<<GEMM_GRID, 256, GEMM_SMEM>>>(x, W1, n);     // idx 3 (profiled)
    sacc_kernel<<<(n * 32 + 255) / 256, 256>>>(n);             // idx 4
    fused_conv_kernel<<<1776, 256>>>(b1, n);                   // idx 5
    final_kernel<<<1, 64>>>(W2, b2, out, n);                   // idx 6
}

// round 12
// speedup vs baseline: 1.3941x; 1.0708x over previous
#include <cuda_runtime.h>
#include <cuda_bf16.h>
#include <cstdint>

#define IN_DIM  128
#define HID_DIM 128
#define OUT_DIM 64
#define MAX_N   100000
#define MAX_E   1700000
#define STRIDE  96

#define WS_BYTES   (128 * 136 * 2)            // 34816
#define AS_PITCH   132
#define AS_BYTES   (64 * AS_PITCH * 4)        // 33792 per buffer
#define GEMM_SMEM  (WS_BYTES + 2 * AS_BYTES)  // 102400
#define GEMM_GRID  296

#define ADD_BF16X2(d, a, b) \
    asm("add.rn.bf16x2 %0, %1, %2;" : "=r"(d) : "r"(a), "r"(b))

// ---------------- device scratch ----------------
__device__ int   g_cnt[MAX_N];                    // in-degree (no self loop)
__device__ float g_dinv[MAX_N];
__device__ float g_s[MAX_N];
__device__ int   g_bin2[(size_t)MAX_N * STRIDE];  // fixed-stride in-neighbor bins
__device__ __nv_bfloat16 g_h0bf[(size_t)MAX_N * HID_DIM];  // dinv[v]*(x@W1)[v]
__device__ float g_y[HID_DIM];
__device__ int   g_is32;

__device__ __forceinline__ int load_idx(const void* ei, size_t i) {
    if (g_is32) return ((const int*)ei)[i];
    return (int)((const long long*)ei)[i];
}

// ------------- init: zero counters + dtype detect + zero y -----------
__global__ void init_kernel(const void* ei, int n) {
    int i = blockIdx.x * blockDim.x + threadIdx.x;
    if (i < n) g_cnt[i] = 0;
    if (i < 128) g_y[i] = 0.f;
    if (i == 0) {
        const long long* p = (const long long*)ei;
        int bad = 0;
        for (int k = 0; k < 8; k++) {
            long long v = p[k];
            if (v < 0 || v >= (long long)n) bad = 1;
        }
        g_is32 = bad;
    }
}

// ------------- binA: one edge pass does count + bin fill -------------
__global__ void binA_kernel(const void* ei, int E) {
    int e = blockIdx.x * blockDim.x + threadIdx.x;
    if (e >= E) return;
    int r = load_idx(ei, e);
    int c = load_idx(ei, (size_t)E + e);
    int pos = atomicAdd(&g_cnt[c], 1);
    if (pos < STRIDE) g_bin2[(unsigned)c * STRIDE + pos] = r;
}

// ------------- dinv from counts -------------
__global__ void dinv_kernel(int n) {
    int i = blockIdx.x * blockDim.x + threadIdx.x;
    if (i < n) {
        float d = rsqrtf((float)(g_cnt[i] + 1));
        g_dinv[i] = d;
        g_s[i] = d;
    }
}

// ---- GEMM1: persistent CTAs, cp.async double-buffered 64-row tiles ----
__device__ __forceinline__ uint32_t packbf(float2 v) {
    __nv_bfloat162 b = __floats2bfloat162_rn(v.x, v.y);
    return *(uint32_t*)&b;
}

__device__ __forceinline__ void cpasync16(void* dst, const void* src) {
    uint32_t d = (uint32_t)__cvta_generic_to_shared(dst);
    asm volatile("cp.async.cg.shared.global [%0], [%1], 16;" :: "r"(d), "l"(src));
}

__global__ __launch_bounds__(256) void gemm1_kernel(
    const float* __restrict__ x, const float* __restrict__ W, int n)
{
    extern __shared__ char smem[];
    __nv_bfloat16 (*Ws)[136] = (__nv_bfloat16(*)[136])smem;          // [128][136]
    float* As = (float*)(smem + WS_BYTES);   // 2 buffers of [64][AS_PITCH]

    int t = threadIdx.x;
    int ntiles = (n + 63) >> 6;

    // load W (once): transposed bf16 [n][k]
    const float4* wg = (const float4*)W;
    #pragma unroll
    for (int i = 0; i < 16; i++) {
        int idx4 = t + i * 256;
        int k = idx4 >> 5, n4 = idx4 & 31;
        float4 v = wg[idx4];
        Ws[n4 * 4 + 0][k] = __float2bfloat16(v.x);
        Ws[n4 * 4 + 1][k] = __float2bfloat16(v.y);
        Ws[n4 * 4 + 2][k] = __float2bfloat16(v.z);
        Ws[n4 * 4 + 3][k] = __float2bfloat16(v.w);
    }

    int lane = t & 31, wid = t >> 5;
    int moff = (wid & 3) * 16;      // 4 M-groups x 16 rows = 64
    int noff = (wid >> 2) * 64;     // 2 N-groups x 64 cols
    int g = lane >> 2, tq = lane & 3;

    // prefetch first tile into buf 0
    int tile0 = blockIdx.x;
    {
        int row0 = tile0 < ntiles ? tile0 * 64 : 0;
        #pragma unroll
        for (int i = 0; i < 8; i++) {
            int idx = t + i * 256;           // 2048 float4 slots
            int r = idx >> 5, c4 = idx & 31;
            int grow = row0 + r; if (grow >= n) grow = n - 1;
            cpasync16(&As[r * AS_PITCH + c4 * 4],
                      x + (size_t)grow * 128 + c4 * 4);
        }
        asm volatile("cp.async.commit_group;");
    }
    __syncthreads();   // Ws ready (also joins prologue)

    int buf = 0;
    for (int tile = tile0; tile < ntiles; tile += GEMM_GRID) {
        // prefetch next tile into buf^1
        {
            int nt2 = tile + GEMM_GRID;
            int row0 = (nt2 < ntiles) ? nt2 * 64 : tile * 64;
            float* dstb = As + (buf ^ 1) * (64 * AS_PITCH);
            #pragma unroll
            for (int i = 0; i < 8; i++) {
                int idx = t + i * 256;
                int r = idx >> 5, c4 = idx & 31;
                int grow = row0 + r; if (grow >= n) grow = n - 1;
                cpasync16(&dstb[r * AS_PITCH + c4 * 4],
                          x + (size_t)grow * 128 + c4 * 4);
            }
            asm volatile("cp.async.commit_group;");
        }
        asm volatile("cp.async.wait_group 1;");   // current tile resident
        __syncthreads();

        const float* Ab = As + buf * (64 * AS_PITCH);
        float acc[8][4];
        #pragma unroll
        for (int nt = 0; nt < 8; nt++)
            #pragma unroll
            for (int j = 0; j < 4; j++) acc[nt][j] = 0.f;

        #pragma unroll
        for (int kt = 0; kt < 8; kt++) {
            int k0 = kt * 16;
            int r = moff + g;
            uint32_t a0 = packbf(*(const float2*)&Ab[r * AS_PITCH + k0 + 2 * tq]);
            uint32_t a1 = packbf(*(const float2*)&Ab[(r + 8) * AS_PITCH + k0 + 2 * tq]);
            uint32_t a2 = packbf(*(const float2*)&Ab[r * AS_PITCH + k0 + 2 * tq + 8]);
            uint32_t a3 = packbf(*(const float2*)&Ab[(r + 8) * AS_PITCH + k0 + 2 * tq + 8]);
            #pragma unroll
            for (int nt = 0; nt < 8; nt++) {
                int c = noff + nt * 8 + g;
                uint32_t b0 = *(const uint32_t*)&Ws[c][k0 + 2 * tq];
                uint32_t b1 = *(const uint32_t*)&Ws[c][k0 + 2 * tq + 8];
                asm volatile(
                    "mma.sync.aligned.m16n8k16.row.col.f32.bf16.bf16.f32 "
                    "{%0,%1,%2,%3}, {%4,%5,%6,%7}, {%8,%9}, {%0,%1,%2,%3};"
                    : "+f"(acc[nt][0]), "+f"(acc[nt][1]),
                      "+f"(acc[nt][2]), "+f"(acc[nt][3])
                    : "r"(a0), "r"(a1), "r"(a2), "r"(a3),
                      "r"(b0), "r"(b1));
            }
        }

        // epilogue: scale by dinv, store bf16
        {
            int r = tile * 64 + moff + g;
            float d0 = (r < n) ? g_dinv[r] : 0.f;
            float d1 = (r + 8 < n) ? g_dinv[r + 8] : 0.f;
            #pragma unroll
            for (int nt = 0; nt < 8; nt++) {
                int c = noff + nt * 8 + 2 * tq;
                if (r < n)
                    *(__nv_bfloat162*)&g_h0bf[(size_t)r * 128 + c] =
                        __floats2bfloat162_rn(d0 * acc[nt][0], d0 * acc[nt][1]);
                if (r + 8 < n)
                    *(__nv_bfloat162*)&g_h0bf[(size_t)(r + 8) * 128 + c] =
                        __floats2bfloat162_rn(d1 * acc[nt][2], d1 * acc[nt][3]);
            }
        }
        __syncthreads();   // all reads of buf done before next prefetch overwrites
        buf ^= 1;
    }
}

// ------------- sacc from bins: s[src] += dinv[v] for src in bin[v] ---------
__global__ void sacc_kernel(int n) {
    int w = (blockIdx.x * blockDim.x + threadIdx.x) >> 5;
    int lane = threadIdx.x & 31;
    if (w >= n) return;
    float dv = g_dinv[w];
    int cnt = min(g_cnt[w], STRIDE);
    unsigned base = (unsigned)w * STRIDE;
    for (int k = lane; k < cnt; k += 32)
        atomicAdd(&g_s[g_bin2[base + k]], dv);
}

// ---------------- fused conv1 + relu + weighted reduce ---------------------
// Inner accumulation in packed bf16 (add.rn.bf16x2): 2 HADD2 per gathered
// uint2 instead of 2 unpack + 4 FADD. Banks split even/odd edges.
__global__ __launch_bounds__(256) void fused_conv_kernel(
    const float* __restrict__ b1, int n)
{
    __shared__ float ysh[8 * 128];
    int t = threadIdx.x, lane = t & 31, w = t >> 5;
    float4 bb = ((const float4*)b1)[lane];
    float4 yacc = make_float4(0.f, 0.f, 0.f, 0.f);
    const uint2* h = (const uint2*)g_h0bf;   // 32 x 8B per row

    int gw = blockIdx.x * 8 + w;
    int nw = gridDim.x * 8;
    for (int v = gw; v < n; v += nw) {
        float dv = g_dinv[v];
        int cnt = min(g_cnt[v], STRIDE);
        unsigned binrow = (unsigned)v * STRIDE;

        uint32_t ax0, ay0, ax1, ay1;
        {   // self loop seeds bank 0 (h already *dinv)
            uint2 us = h[(unsigned)v * 32 + lane];
            ax0 = us.x; ay0 = us.y;
            ax1 = 0u;   ay1 = 0u;   // bf16x2 (+0,+0)
        }

        for (int kb = 0; kb < cnt; kb += 32) {
            int m = min(cnt - kb, 32);
            int myidx = (lane < m) ? g_bin2[binrow + kb + lane] : 0;  // coalesced
            int j = 0;
            for (; j + 2 <= m; j += 2) {
                int s0 = __shfl_sync(0xffffffffu, myidx, j);
                int s1 = __shfl_sync(0xffffffffu, myidx, j + 1);
                uint2 u0 = h[(unsigned)s0 * 32 + lane];
                uint2 u1 = h[(unsigned)s1 * 32 + lane];
                ADD_BF16X2(ax0, ax0, u0.x);
                ADD_BF16X2(ay0, ay0, u0.y);
                ADD_BF16X2(ax1, ax1, u1.x);
                ADD_BF16X2(ay1, ay1, u1.y);
            }
            if (j < m) {
                int s0 = __shfl_sync(0xffffffffu, myidx, j);
                uint2 u0 = h[(unsigned)s0 * 32 + lane];
                ADD_BF16X2(ax1, ax1, u0.x);
                ADD_BF16X2(ay1, ay1, u0.y);
            }
        }

        // combine banks in fp32
        float2 fx0 = __bfloat1622float2(*(__nv_bfloat162*)&ax0);
        float2 fx1 = __bfloat1622float2(*(__nv_bfloat162*)&ax1);
        float2 fy0 = __bfloat1622float2(*(__nv_bfloat162*)&ay0);
        float2 fy1 = __bfloat1622float2(*(__nv_bfloat162*)&ay1);
        float sx = fx0.x + fx1.x, sy = fx0.y + fx1.y;
        float sz = fy0.x + fy1.x, sw = fy0.y + fy1.y;

        float cv = dv * g_s[v];
        yacc.x = fmaf(cv, fmaxf(fmaf(dv, sx, bb.x), 0.f), yacc.x);
        yacc.y = fmaf(cv, fmaxf(fmaf(dv, sy, bb.y), 0.f), yacc.y);
        yacc.z = fmaf(cv, fmaxf(fmaf(dv, sz, bb.z), 0.f), yacc.z);
        yacc.w = fmaf(cv, fmaxf(fmaf(dv, sw, bb.w), 0.f), yacc.w);
    }

    *((float4*)&ysh[w * 128 + lane * 4]) = yacc;
    __syncthreads();
    if (t < 128) {
        float s = 0.f;
        #pragma unroll
        for (int i = 0; i < 8; i++) s += ysh[i * 128 + t];
        atomicAdd(&g_y[t], s);
    }
}

// ---------------- final: out = (y @ W2)/N + b2 ----------------
__global__ void final_kernel(const float* __restrict__ W2,
                             const float* __restrict__ b2,
                             float* __restrict__ out, int n)
{
    int f = threadIdx.x;   // 64
    float sum = 0.f;
    #pragma unroll 8
    for (int k = 0; k < 128; k++)
        sum = fmaf(g_y[k], W2[k * 64 + f], sum);
    out[f] = sum / (float)n + b2[f];
}

// ---------------- launch ----------------
extern "C" void kernel_launch(void* const* d_in, const int* in_sizes, int n_in,
                              void* d_out, int out_size)
{
    const float* x  = (const float*)d_in[0];
    const void*  ei = d_in[1];
    const float* W1 = (const float*)d_in[2];
    const float* b1 = (const float*)d_in[3];
    const float* W2 = (const float*)d_in[4];
    const float* b2 = (const float*)d_in[5];
    float* out = (float*)d_out;

    int n = in_sizes[0] / IN_DIM;     // 100000
    int E = in_sizes[1] / 2;          // 1600000

    cudaFuncSetAttribute(gemm1_kernel,
                         cudaFuncAttributeMaxDynamicSharedMemorySize, GEMM_SMEM);

    init_kernel<<<(n + 255) / 256, 256>>>(ei, n);              // idx 0
    binA_kernel<<<(E + 255) / 256, 256>>>(ei, E);              // idx 1
    dinv_kernel<<<(n + 255) / 256, 256>>>(n);                  // idx 2
    gemm1_kernel<<<GEMM_GRID, 256, GEMM_SMEM>>>(x, W1, n);     // idx 3 (profiled)
    sacc_kernel<<<(n * 32 + 255) / 256, 256>>>(n);             // idx 4
    fused_conv_kernel<<<1776, 256>>>(b1, n);                   // idx 5
    final_kernel<<<1, 64>>>(W2, b2, out, n);                   // idx 6
}